// round 8
// baseline (speedup 1.0000x reference)
#include <cuda_runtime.h>
#include <cstdint>

namespace {

constexpr int Bz  = 4;
constexpr int NHn = 4;
constexpr int Tn  = 512;
constexpr int Dn  = 256;
constexpr int Nn  = 8192;
constexpr int BHn = Bz * NHn;
constexpr float SCALEF = 0.011048543456039806f;  // N^-0.5

// Scratch (device globals; allocation-free per harness rules)
__device__ float g_qr[(size_t)BHn * Tn * Nn];   // 256 MB RoPE'd Q  (t,n)
__device__ float g_sc[(size_t)BHn * Tn * Tn];   // 16 MB masked scores (t,s)

// ---------------------------------------------------------------------------
// Tiling (identical to the round-5 passing kernel; SMEM holds tf32 bits)
// ---------------------------------------------------------------------------
constexpr int BM = 128, BN = 128, BK = 32;
constexpr int ASTR = BK + 4;    // 36 words: A row stride (conflict-free frags)
constexpr int BSTR = BN + 8;    // 136 words: B row stride (conflict-free frags)
constexpr int ASZ = BM * ASTR;  // 4608 words
constexpr int BSZ = BK * BSTR;  // 4352 words
constexpr int SMEM_TOTAL = 2 * (ASZ + BSZ) * 4;  // 71680 B

__device__ __forceinline__ uint32_t f2t(float x) {
    uint32_t u;
    asm("cvt.rna.tf32.f32 %0, %1;" : "=r"(u) : "f"(x));
    return u;
}

__device__ __forceinline__ void mma_tf32(float c[4], const uint32_t a[4],
                                         const uint32_t b[2]) {
    asm volatile(
        "mma.sync.aligned.m16n8k8.row.col.f32.tf32.tf32.f32 "
        "{%0,%1,%2,%3}, {%4,%5,%6,%7}, {%8,%9}, {%0,%1,%2,%3};"
        : "+f"(c[0]), "+f"(c[1]), "+f"(c[2]), "+f"(c[3])
        : "r"(a[0]), "r"(a[1]), "r"(a[2]), "r"(a[3]), "r"(b[0]), "r"(b[1]));
}

// One k-octet (k8) of the 64x32 warp tile from SMEM (tf32 bits, plain LDS).
__device__ __forceinline__ void mma_octet(const uint32_t* __restrict__ As,
                                          const uint32_t* __restrict__ Bs,
                                          int ko, int wm, int wn,
                                          int gid, int tig, float c[16][4]) {
    uint32_t a[4][4], b[4][2];
#pragma unroll
    for (int im = 0; im < 4; ++im) {
        const uint32_t* pa = As + (wm + im * 16 + gid) * ASTR + ko + tig;
        a[im][0] = pa[0];
        a[im][1] = pa[8 * ASTR];
        a[im][2] = pa[4];
        a[im][3] = pa[8 * ASTR + 4];
    }
#pragma unroll
    for (int jn = 0; jn < 4; ++jn) {
        const uint32_t* pb = Bs + (ko + tig) * BSTR + wn + jn * 8 + gid;
        b[jn][0] = pb[0];
        b[jn][1] = pb[4 * BSTR];
    }
#pragma unroll
    for (int im = 0; im < 4; ++im)
#pragma unroll
        for (int jn = 0; jn < 4; ++jn)
            mma_tf32(c[im * 4 + jn], a[im], b[jn]);
}

// ---------------------------------------------------------------------------
// Staging: global fp32 -> regs -> tf32 SMEM (double-buffered pipeline)
// ---------------------------------------------------------------------------
// A direct: src (m,k) row-major, row stride ld. thread -> 4x float4.
__device__ __forceinline__ void ldA_dir(const float* src, int ld, float4 r[4]) {
    int m = threadIdx.x >> 3, kc = (threadIdx.x & 7) * 4;
#pragma unroll
    for (int i = 0; i < 4; ++i)
        r[i] = *reinterpret_cast<const float4*>(src + (size_t)(m + i * 32) * ld + kc);
}
__device__ __forceinline__ void stA_dir(uint32_t* As, const float4 r[4]) {
    int m = threadIdx.x >> 3, kc = (threadIdx.x & 7) * 4;
#pragma unroll
    for (int i = 0; i < 4; ++i) {
        uint4 v;
        v.x = f2t(r[i].x); v.y = f2t(r[i].y); v.z = f2t(r[i].z); v.w = f2t(r[i].w);
        *reinterpret_cast<uint4*>(As + (m + i * 32) * ASTR + kc) = v;
    }
}
// A transposed: src (k,m) row-major (ld along m). As[m][k].
__device__ __forceinline__ void ldA_tr(const float* src, int ld, float4 r[4]) {
    int k = threadIdx.x >> 5, mc = (threadIdx.x & 31) * 4;
#pragma unroll
    for (int i = 0; i < 4; ++i)
        r[i] = *reinterpret_cast<const float4*>(src + (size_t)(k + i * 8) * ld + mc);
}
__device__ __forceinline__ void stA_tr(uint32_t* As, const float4 r[4]) {
    int k = threadIdx.x >> 5, mc = (threadIdx.x & 31) * 4;
#pragma unroll
    for (int i = 0; i < 4; ++i) {
        int kk = k + i * 8;
        As[(mc + 0) * ASTR + kk] = f2t(r[i].x);
        As[(mc + 1) * ASTR + kk] = f2t(r[i].y);
        As[(mc + 2) * ASTR + kk] = f2t(r[i].z);
        As[(mc + 3) * ASTR + kk] = f2t(r[i].w);
    }
}
// B direct: src (k,n) row-major. Bs[k][n].
__device__ __forceinline__ void ldB_dir(const float* src, int ld, float4 r[4]) {
    int k = threadIdx.x >> 5, nc = (threadIdx.x & 31) * 4;
#pragma unroll
    for (int i = 0; i < 4; ++i)
        r[i] = *reinterpret_cast<const float4*>(src + (size_t)(k + i * 8) * ld + nc);
}
__device__ __forceinline__ void stB_dir(uint32_t* Bs, const float4 r[4]) {
    int k = threadIdx.x >> 5, nc = (threadIdx.x & 31) * 4;
#pragma unroll
    for (int i = 0; i < 4; ++i) {
        uint4 v;
        v.x = f2t(r[i].x); v.y = f2t(r[i].y); v.z = f2t(r[i].z); v.w = f2t(r[i].w);
        *reinterpret_cast<uint4*>(Bs + (k + i * 8) * BSTR + nc) = v;
    }
}
// B transposed: src (n,k) row-major. Bs[k][n].
__device__ __forceinline__ void ldB_tr(const float* src, int ld, float4 r[4]) {
    int n = threadIdx.x >> 3, kc = (threadIdx.x & 7) * 4;
#pragma unroll
    for (int i = 0; i < 4; ++i)
        r[i] = *reinterpret_cast<const float4*>(src + (size_t)(n + i * 32) * ld + kc);
}
__device__ __forceinline__ void stB_tr(uint32_t* Bs, const float4 r[4]) {
    int n = threadIdx.x >> 3, kc = (threadIdx.x & 7) * 4;
#pragma unroll
    for (int i = 0; i < 4; ++i) {
        int nn = n + i * 32;
        Bs[(kc + 0) * BSTR + nn] = f2t(r[i].x);
        Bs[(kc + 1) * BSTR + nn] = f2t(r[i].y);
        Bs[(kc + 2) * BSTR + nn] = f2t(r[i].z);
        Bs[(kc + 3) * BSTR + nn] = f2t(r[i].w);
    }
}

// ---------------------------------------------------------------------------
// K1: RoPE -> g_qr (fp32)
// ---------------------------------------------------------------------------
__global__ void rope_kernel(const float* __restrict__ Q,
                            const float* __restrict__ C,
                            const float* __restrict__ S) {
    constexpr int PR = Nn / 2;
    size_t tid = (size_t)blockIdx.x * blockDim.x + threadIdx.x;  // pair index
    int t  = (int)((tid / PR) % Tn);
    int n2 = (int)(tid % PR);
    float2 q = reinterpret_cast<const float2*>(Q)[tid];
    float2 c = reinterpret_cast<const float2*>(C)[(size_t)t * PR + n2];
    float2 s = reinterpret_cast<const float2*>(S)[(size_t)t * PR + n2];
    float2 r;
    r.x = q.x * c.x - q.y * s.x;
    r.y = q.y * c.y + q.x * s.y;
    reinterpret_cast<float2*>(g_qr)[tid] = r;
}

// ---------------------------------------------------------------------------
// K2: scores = mask(QR @ QR^T) * SCALE (lower-tri tiles only)
// grid (4, 4, 16): x = s-tile, y = t-tile, z = bh.
// ---------------------------------------------------------------------------
__global__ void __launch_bounds__(256, 1) scores_gemm() {
    const int sb = blockIdx.x, tb = blockIdx.y, bh = blockIdx.z;
    if (sb > tb) return;
    extern __shared__ uint32_t sm[];
    uint32_t* As[2] = {sm, sm + ASZ};
    uint32_t* Bs[2] = {sm + 2 * ASZ, sm + 2 * ASZ + BSZ};

    const int t0 = tb * BM, s0 = sb * BN;
    const int lane = threadIdx.x & 31, wid = threadIdx.x >> 5;
    const int gid = lane >> 2, tig = lane & 3;
    const int wm = (wid & 1) * 64, wn = (wid >> 1) * 32;
    const float* Asrc = g_qr + ((size_t)bh * Tn + t0) * Nn;
    const float* Bsrc = g_qr + ((size_t)bh * Tn + s0) * Nn;

    float c[16][4] = {};
    constexpr int KT = Nn / BK;  // 256

    float4 ra[4], rb[4];
    ldA_dir(Asrc, Nn, ra); ldB_tr(Bsrc, Nn, rb);
    stA_dir(As[0], ra);    stB_tr(Bs[0], rb);
    __syncthreads();

    int cur = 0;
    for (int kt = 0; kt < KT; ++kt) {
        bool nxt = kt + 1 < KT;
        if (nxt) {
            ldA_dir(Asrc + (kt + 1) * BK, Nn, ra);
            ldB_tr (Bsrc + (kt + 1) * BK, Nn, rb);
        }
#pragma unroll
        for (int ko = 0; ko < BK; ko += 8)
            mma_octet(As[cur], Bs[cur], ko, wm, wn, gid, tig, c);
        if (nxt) { stA_dir(As[cur ^ 1], ra); stB_tr(Bs[cur ^ 1], rb); }
        __syncthreads();
        cur ^= 1;
    }

    float* Sc = g_sc + (size_t)bh * Tn * Tn;
#pragma unroll
    for (int im = 0; im < 4; ++im)
#pragma unroll
        for (int jn = 0; jn < 4; ++jn) {
            int t = t0 + wm + im * 16 + gid;
            int s = s0 + wn + jn * 8 + tig * 2;
            float* cc = c[im * 4 + jn];
            Sc[(size_t)t * Tn + s]           = (s     < t) ? cc[0] * SCALEF : 0.f;
            Sc[(size_t)t * Tn + s + 1]       = (s + 1 < t) ? cc[1] * SCALEF : 0.f;
            Sc[(size_t)(t + 8) * Tn + s]     = (s     < t + 8) ? cc[2] * SCALEF : 0.f;
            Sc[(size_t)(t + 8) * Tn + s + 1] = (s + 1 < t + 8) ? cc[3] * SCALEF : 0.f;
        }
}

// ---------------------------------------------------------------------------
// K3: out = scores @ V + QR @ state  (two K-segments, one accumulator)
// grid (2, 4, 16): x = d-tile, y = t-tile, z = bh
// ---------------------------------------------------------------------------
__global__ void __launch_bounds__(256, 1) out_gemm(const float* __restrict__ V,
                                                   const float* __restrict__ state,
                                                   float* __restrict__ out) {
    extern __shared__ uint32_t sm[];
    uint32_t* As[2] = {sm, sm + ASZ};
    uint32_t* Bs[2] = {sm + 2 * ASZ, sm + 2 * ASZ + BSZ};

    const int db = blockIdx.x, tb = blockIdx.y, bh = blockIdx.z, b = bh >> 2;
    const int t0 = tb * BM, d0 = db * BN;
    const int lane = threadIdx.x & 31, wid = threadIdx.x >> 5;
    const int gid = lane >> 2, tig = lane & 3;
    const int wm = (wid & 1) * 64, wn = (wid >> 1) * 32;

    const float* A1 = g_sc + ((size_t)bh * Tn + t0) * Tn;
    const float* B1 = V + (size_t)b * Tn * Dn + d0;
    const float* A2 = g_qr + ((size_t)bh * Tn + t0) * Nn;
    const float* B2 = state + (size_t)bh * Nn * Dn + d0;

    const int KT1 = (tb + 1) * (BM / BK);   // causal trim: s < (tb+1)*128
    const int KT = KT1 + Nn / BK;

    float c[16][4] = {};
    float4 ra[4], rb[4];

    auto ld_iter = [&](int kt, float4 a[4], float4 bbr[4]) {
        if (kt < KT1) {
            ldA_dir(A1 + kt * BK, Tn, a);
            ldB_dir(B1 + (size_t)kt * BK * Dn, Dn, bbr);
        } else {
            int k2 = kt - KT1;
            ldA_dir(A2 + k2 * BK, Nn, a);
            ldB_dir(B2 + (size_t)k2 * BK * Dn, Dn, bbr);
        }
    };

    ld_iter(0, ra, rb);
    stA_dir(As[0], ra); stB_dir(Bs[0], rb);
    __syncthreads();

    int cur = 0;
    for (int kt = 0; kt < KT; ++kt) {
        bool nxt = kt + 1 < KT;
        if (nxt) ld_iter(kt + 1, ra, rb);
#pragma unroll
        for (int ko = 0; ko < BK; ko += 8)
            mma_octet(As[cur], Bs[cur], ko, wm, wn, gid, tig, c);
        if (nxt) { stA_dir(As[cur ^ 1], ra); stB_dir(Bs[cur ^ 1], rb); }
        __syncthreads();
        cur ^= 1;
    }

    float* O = out + ((size_t)bh * Tn + t0) * Dn + d0;
#pragma unroll
    for (int im = 0; im < 4; ++im)
#pragma unroll
        for (int jn = 0; jn < 4; ++jn) {
            int r = wm + im * 16 + gid;
            int cN = wn + jn * 8 + tig * 2;
            float* cc = c[im * 4 + jn];
            O[(size_t)r * Dn + cN]           = cc[0];
            O[(size_t)r * Dn + cN + 1]       = cc[1];
            O[(size_t)(r + 8) * Dn + cN]     = cc[2];
            O[(size_t)(r + 8) * Dn + cN + 1] = cc[3];
        }
}

// ---------------------------------------------------------------------------
// K4: new_state = state + SCALE * QR^T @ V
// grid (2, 64, 16): x = d-tile, y = n-tile, z = bh
// ---------------------------------------------------------------------------
__global__ void __launch_bounds__(256, 1) nstate_gemm(const float* __restrict__ V,
                                                      const float* __restrict__ state,
                                                      float* __restrict__ outns) {
    extern __shared__ uint32_t sm[];
    uint32_t* As[2] = {sm, sm + ASZ};
    uint32_t* Bs[2] = {sm + 2 * ASZ, sm + 2 * ASZ + BSZ};

    const int db = blockIdx.x, nb = blockIdx.y, bh = blockIdx.z, b = bh >> 2;
    const int n0 = nb * BM, d0 = db * BN;
    const int lane = threadIdx.x & 31, wid = threadIdx.x >> 5;
    const int gid = lane >> 2, tig = lane & 3;
    const int wm = (wid & 1) * 64, wn = (wid >> 1) * 32;

    const float* Asrc = g_qr + (size_t)bh * Tn * Nn + n0;  // (t, n): k rows, m cols
    const float* Bsrc = V + (size_t)b * Tn * Dn + d0;      // (t, d)

    float c[16][4] = {};
    constexpr int KT = Tn / BK;  // 16

    float4 ra[4], rb[4];
    ldA_tr(Asrc, Nn, ra); ldB_dir(Bsrc, Dn, rb);
    stA_tr(As[0], ra);    stB_dir(Bs[0], rb);
    __syncthreads();

    int cur = 0;
    for (int kt = 0; kt < KT; ++kt) {
        bool nxt = kt + 1 < KT;
        if (nxt) {
            ldA_tr (Asrc + (size_t)(kt + 1) * BK * Nn, Nn, ra);
            ldB_dir(Bsrc + (size_t)(kt + 1) * BK * Dn, Dn, rb);
        }
#pragma unroll
        for (int ko = 0; ko < BK; ko += 8)
            mma_octet(As[cur], Bs[cur], ko, wm, wn, gid, tig, c);
        if (nxt) { stA_tr(As[cur ^ 1], ra); stB_dir(Bs[cur ^ 1], rb); }
        __syncthreads();
        cur ^= 1;
    }

    const float* St = state + ((size_t)bh * Nn + n0) * Dn + d0;
    float* O = outns + ((size_t)bh * Nn + n0) * Dn + d0;
#pragma unroll
    for (int im = 0; im < 4; ++im)
#pragma unroll
        for (int jn = 0; jn < 4; ++jn) {
            int r = wm + im * 16 + gid;
            int cN = wn + jn * 8 + tig * 2;
            float* cc = c[im * 4 + jn];
            O[(size_t)r * Dn + cN]           = St[(size_t)r * Dn + cN]           + SCALEF * cc[0];
            O[(size_t)r * Dn + cN + 1]       = St[(size_t)r * Dn + cN + 1]       + SCALEF * cc[1];
            O[(size_t)(r + 8) * Dn + cN]     = St[(size_t)(r + 8) * Dn + cN]     + SCALEF * cc[2];
            O[(size_t)(r + 8) * Dn + cN + 1] = St[(size_t)(r + 8) * Dn + cN + 1] + SCALEF * cc[3];
        }
}

}  // namespace

extern "C" void kernel_launch(void* const* d_in, const int* in_sizes, int n_in,
                              void* d_out, int out_size) {
    const float* Q     = (const float*)d_in[0];
    const float* V     = (const float*)d_in[1];
    const float* state = (const float*)d_in[2];
    const float* cosb  = (const float*)d_in[3];
    const float* sinb  = (const float*)d_in[4];
    float* out = (float*)d_out;

    cudaFuncSetAttribute(scores_gemm, cudaFuncAttributeMaxDynamicSharedMemorySize, SMEM_TOTAL);
    cudaFuncSetAttribute(out_gemm,    cudaFuncAttributeMaxDynamicSharedMemorySize, SMEM_TOTAL);
    cudaFuncSetAttribute(nstate_gemm, cudaFuncAttributeMaxDynamicSharedMemorySize, SMEM_TOTAL);

    rope_kernel<<<(unsigned)((size_t)BHn * Tn * (Nn / 2) / 256), 256>>>(Q, cosb, sinb);
    scores_gemm<<<dim3(4, 4, BHn), 256, SMEM_TOTAL>>>();
    out_gemm<<<dim3(2, 4, BHn), 256, SMEM_TOTAL>>>(V, state, out);
    nstate_gemm<<<dim3(2, Nn / BM, BHn), 256, SMEM_TOTAL>>>(
        V, state, out + (size_t)BHn * Tn * Dn);
}

// round 9
// speedup vs baseline: 1.7102x; 1.7102x over previous
#include <cuda_runtime.h>
#include <cstdint>

namespace {

constexpr int Bz  = 4;
constexpr int NHn = 4;
constexpr int Tn  = 512;
constexpr int Dn  = 256;
constexpr int Nn  = 8192;
constexpr int BHn = Bz * NHn;
constexpr float SCALEF = 0.011048543456039806f;  // N^-0.5

// Scratch (device globals; allocation-free). All values tf32-pre-rounded fp32.
__device__ float g_qr[(size_t)BHn * Tn * Nn];   // RoPE(Q)    (t,n)
__device__ float g_qt[(size_t)BHn * Nn * Tn];   // RoPE(Q)^T  (n,t)
__device__ float g_st[(size_t)BHn * Dn * Nn];   // state^T    (d,n)
__device__ float g_vt[(size_t)Bz * Dn * Tn];    // V^T        (d,t)
__device__ float g_sc[(size_t)BHn * Tn * Tn];   // masked scores (t,s)

// ---------------------------------------------------------------------------
// Tiling: BM=BN=128, BK=32. All SMEM tiles [128 rows][36 words] (pad 4).
// 8 warps as 2(m) x 4(n); warp tile 64x32. 4-stage cp.async pipeline.
// ---------------------------------------------------------------------------
constexpr int BM = 128, BK = 32;
constexpr int RSTR = 36;
constexpr int TILE_WORDS = BM * RSTR;            // 4608
constexpr int STG = 4;
constexpr int SMEM_TOTAL = STG * 2 * TILE_WORDS * 4;   // 147456 B

__device__ __forceinline__ uint32_t f2t(float x) {
    uint32_t u;
    asm("cvt.rna.tf32.f32 %0, %1;" : "=r"(u) : "f"(x));
    return u;
}
__device__ __forceinline__ float f2tf(float x) { return __uint_as_float(f2t(x)); }

__device__ __forceinline__ uint32_t smem_u32(const void* p) {
    uint32_t a;
    asm("{ .reg .u64 t; cvta.to.shared.u64 t, %1; cvt.u32.u64 %0, t; }"
        : "=r"(a) : "l"(p));
    return a;
}

__device__ __forceinline__ void mma_tf32(float c[4], const uint32_t a[4],
                                         const uint32_t b[2]) {
    asm volatile(
        "mma.sync.aligned.m16n8k8.row.col.f32.tf32.tf32.f32 "
        "{%0,%1,%2,%3}, {%4,%5,%6,%7}, {%8,%9}, {%0,%1,%2,%3};"
        : "+f"(c[0]), "+f"(c[1]), "+f"(c[2]), "+f"(c[3])
        : "r"(a[0]), "r"(a[1]), "r"(a[2]), "r"(a[3]), "r"(b[0]), "r"(b[1]));
}

// One k-octet of the 64x32 warp tile. A,B both [128][36] row-major.
__device__ __forceinline__ void mma_oct(const uint32_t* __restrict__ As,
                                        const uint32_t* __restrict__ Bs,
                                        int ko, int wm, int wn,
                                        int gid, int tig, float c[16][4]) {
    uint32_t a[4][4], b[4][2];
#pragma unroll
    for (int im = 0; im < 4; ++im) {
        const uint32_t* pa = As + (wm + im * 16 + gid) * RSTR + ko + tig;
        a[im][0] = pa[0];
        a[im][1] = pa[8 * RSTR];
        a[im][2] = pa[4];
        a[im][3] = pa[8 * RSTR + 4];
    }
#pragma unroll
    for (int jn = 0; jn < 4; ++jn) {
        const uint32_t* pb = Bs + (wn + jn * 8 + gid) * RSTR + ko + tig;
        b[jn][0] = pb[0];
        b[jn][1] = pb[4];
    }
#pragma unroll
    for (int im = 0; im < 4; ++im)
#pragma unroll
        for (int jn = 0; jn < 4; ++jn)
            mma_tf32(c[im * 4 + jn], a[im], b[jn]);
}

// cp.async one [128][32] fp32 tile (k contiguous in source, row stride ld).
__device__ __forceinline__ void cp_tile(uint32_t dbase,
                                        const float* __restrict__ src, int ld) {
#pragma unroll
    for (int i = 0; i < 4; ++i) {
        int ch = threadIdx.x + i * 256;
        int row = ch >> 3, kc = (ch & 7) * 4;
        uint32_t d = dbase + (uint32_t)((row * RSTR + kc) * 4);
        asm volatile("cp.async.cg.shared.global [%0], [%1], 16;"
                     :: "r"(d), "l"(src + (size_t)row * ld + kc));
    }
}
#define CP_COMMIT() asm volatile("cp.async.commit_group;" ::: "memory")
#define CP_WAIT2()  asm volatile("cp.async.wait_group 2;" ::: "memory")

// ---------------------------------------------------------------------------
// Shared GEMM mainloop driver. Fetch(kt) -> {A ptr, lda, B ptr, ldb}.
// ---------------------------------------------------------------------------
struct SrcPair { const float* a; int la; const float* b; int lb; };

template <typename F>
__device__ __forceinline__ void gemm_main(uint32_t sb, const uint32_t* smu,
                                          int KT, F fetch_src,
                                          int wm, int wn, int gid, int tig,
                                          float c[16][4]) {
    auto saddr = [&](int st, int ab) {
        return sb + (uint32_t)(((st * 2 + ab) * TILE_WORDS) * 4);
    };
#pragma unroll
    for (int p = 0; p < STG - 1; ++p) {
        if (p < KT) {
            SrcPair s = fetch_src(p);
            cp_tile(saddr(p, 0), s.a, s.la);
            cp_tile(saddr(p, 1), s.b, s.lb);
        }
        CP_COMMIT();
    }
    for (int kt = 0; kt < KT; ++kt) {
        CP_WAIT2();
        __syncthreads();
        int pf = kt + STG - 1;
        if (pf < KT) {
            SrcPair s = fetch_src(pf);
            cp_tile(saddr(pf & 3, 0), s.a, s.la);
            cp_tile(saddr(pf & 3, 1), s.b, s.lb);
        }
        CP_COMMIT();
        const uint32_t* As = smu + (size_t)(kt & 3) * 2 * TILE_WORDS;
        const uint32_t* Bs = As + TILE_WORDS;
#pragma unroll
        for (int ko = 0; ko < BK; ko += 8)
            mma_oct(As, Bs, ko, wm, wn, gid, tig, c);
    }
}

// ---------------------------------------------------------------------------
// K1: RoPE -> g_qr (t,n) and g_qt (n,t), tf32-rounded
// ---------------------------------------------------------------------------
__global__ void rope_kernel(const float* __restrict__ Q,
                            const float* __restrict__ C,
                            const float* __restrict__ S) {
    __shared__ float tile[32][65];
    const int bh = blockIdx.z, t0 = blockIdx.y * 32, n0 = blockIdx.x * 64;
    const int tid = threadIdx.x;
    const size_t qbase = ((size_t)bh * Tn + t0) * Nn + n0;
#pragma unroll
    for (int i = 0; i < 4; ++i) {
        int p  = tid + i * 256;
        int tt = p >> 5, pi = p & 31;
        int nn = pi * 2;
        float2 q = *reinterpret_cast<const float2*>(Q + qbase + (size_t)tt * Nn + nn);
        float2 c = *reinterpret_cast<const float2*>(C + (size_t)(t0 + tt) * Nn + n0 + nn);
        float2 s = *reinterpret_cast<const float2*>(S + (size_t)(t0 + tt) * Nn + n0 + nn);
        float2 r;
        r.x = f2tf(q.x * c.x - q.y * s.x);
        r.y = f2tf(q.y * c.y + q.x * s.y);
        *reinterpret_cast<float2*>(g_qr + qbase + (size_t)tt * Nn + nn) = r;
        tile[tt][nn] = r.x;
        tile[tt][nn + 1] = r.y;
    }
    __syncthreads();
    const size_t tbase = ((size_t)bh * Nn + n0) * Tn + t0;
#pragma unroll
    for (int i = 0; i < 8; ++i) {
        int e  = tid + i * 256;
        int nn = e >> 5, tt = e & 31;
        g_qt[tbase + (size_t)nn * Tn + tt] = tile[tt][nn];
    }
}

// K1b: state^T (d,n), tf32-rounded
__global__ void stateT_kernel(const float* __restrict__ St) {
    __shared__ float tile[32][33];
    const int bh = blockIdx.z, n0 = blockIdx.x * 32, d0 = blockIdx.y * 32;
    const int tid = threadIdx.x;
#pragma unroll
    for (int i = 0; i < 4; ++i) {
        int e = tid + i * 256;
        int nn = e >> 5, dd = e & 31;
        tile[nn][dd] = St[((size_t)bh * Nn + n0 + nn) * Dn + d0 + dd];
    }
    __syncthreads();
#pragma unroll
    for (int i = 0; i < 4; ++i) {
        int e = tid + i * 256;
        int dd = e >> 5, nn = e & 31;
        g_st[((size_t)bh * Dn + d0 + dd) * Nn + n0 + nn] = f2tf(tile[nn][dd]);
    }
}

// K1c: V^T (d,t), tf32-rounded
__global__ void vT_kernel(const float* __restrict__ V) {
    __shared__ float tile[32][33];
    const int b = blockIdx.z, t0 = blockIdx.x * 32, d0 = blockIdx.y * 32;
    const int tid = threadIdx.x;
#pragma unroll
    for (int i = 0; i < 4; ++i) {
        int e = tid + i * 256;
        int tt = e >> 5, dd = e & 31;
        tile[tt][dd] = V[((size_t)b * Tn + t0 + tt) * Dn + d0 + dd];
    }
    __syncthreads();
#pragma unroll
    for (int i = 0; i < 4; ++i) {
        int e = tid + i * 256;
        int dd = e >> 5, tt = e & 31;
        g_vt[((size_t)b * Dn + d0 + dd) * Tn + t0 + tt] = f2tf(tile[tt][dd]);
    }
}

// ---------------------------------------------------------------------------
// K2: scores = mask(QR @ QR^T) * SCALE (lower-tri tiles only), tf32-rounded
// grid (4, 4, 16)
// ---------------------------------------------------------------------------
__global__ void __launch_bounds__(256, 1) scores_gemm() {
    const int sb_ = blockIdx.x, tb = blockIdx.y, bh = blockIdx.z;
    if (sb_ > tb) return;
    extern __shared__ uint32_t smu[];
    uint32_t sb = smem_u32(smu);

    const int t0 = tb * BM, s0 = sb_ * BM;
    const int lane = threadIdx.x & 31, wid = threadIdx.x >> 5;
    const int gid = lane >> 2, tig = lane & 3;
    const int wm = (wid & 1) * 64, wn = (wid >> 1) * 32;
    const float* Asrc = g_qr + ((size_t)bh * Tn + t0) * Nn;
    const float* Bsrc = g_qr + ((size_t)bh * Tn + s0) * Nn;

    float c[16][4] = {};
    gemm_main(sb, smu, Nn / BK,
              [&](int kt) { return SrcPair{Asrc + kt * BK, Nn, Bsrc + kt * BK, Nn}; },
              wm, wn, gid, tig, c);

    float* Sc = g_sc + (size_t)bh * Tn * Tn;
#pragma unroll
    for (int im = 0; im < 4; ++im)
#pragma unroll
        for (int jn = 0; jn < 4; ++jn) {
            int t = t0 + wm + im * 16 + gid;
            int s = s0 + wn + jn * 8 + tig * 2;
            float* cc = c[im * 4 + jn];
            Sc[(size_t)t * Tn + s]           = (s     < t) ? f2tf(cc[0] * SCALEF) : 0.f;
            Sc[(size_t)t * Tn + s + 1]       = (s + 1 < t) ? f2tf(cc[1] * SCALEF) : 0.f;
            Sc[(size_t)(t + 8) * Tn + s]     = (s     < t + 8) ? f2tf(cc[2] * SCALEF) : 0.f;
            Sc[(size_t)(t + 8) * Tn + s + 1] = (s + 1 < t + 8) ? f2tf(cc[3] * SCALEF) : 0.f;
        }
}

// ---------------------------------------------------------------------------
// K3: out = scores @ V + QR @ state  (two K-segments, one accumulator)
// grid (2, 4, 16)
// ---------------------------------------------------------------------------
__global__ void __launch_bounds__(256, 1) out_gemm(float* __restrict__ out) {
    extern __shared__ uint32_t smu[];
    uint32_t sb = smem_u32(smu);

    const int db = blockIdx.x, tb = blockIdx.y, bh = blockIdx.z, b = bh >> 2;
    const int t0 = tb * BM, d0 = db * BM;
    const int lane = threadIdx.x & 31, wid = threadIdx.x >> 5;
    const int gid = lane >> 2, tig = lane & 3;
    const int wm = (wid & 1) * 64, wn = (wid >> 1) * 32;

    const float* A1 = g_sc + ((size_t)bh * Tn + t0) * Tn;
    const float* B1 = g_vt + ((size_t)b * Dn + d0) * Tn;
    const float* A2 = g_qr + ((size_t)bh * Tn + t0) * Nn;
    const float* B2 = g_st + ((size_t)bh * Dn + d0) * Nn;

    const int KT1 = (tb + 1) * (BM / BK);   // causal trim
    const int KT = KT1 + Nn / BK;

    float c[16][4] = {};
    gemm_main(sb, smu, KT,
              [&](int kt) {
                  if (kt < KT1)
                      return SrcPair{A1 + kt * BK, Tn, B1 + kt * BK, Tn};
                  int k2 = kt - KT1;
                  return SrcPair{A2 + k2 * BK, Nn, B2 + k2 * BK, Nn};
              },
              wm, wn, gid, tig, c);

    float* O = out + ((size_t)bh * Tn + t0) * Dn + d0;
#pragma unroll
    for (int im = 0; im < 4; ++im)
#pragma unroll
        for (int jn = 0; jn < 4; ++jn) {
            int r = wm + im * 16 + gid;
            int cN = wn + jn * 8 + tig * 2;
            float* cc = c[im * 4 + jn];
            O[(size_t)r * Dn + cN]           = cc[0];
            O[(size_t)r * Dn + cN + 1]       = cc[1];
            O[(size_t)(r + 8) * Dn + cN]     = cc[2];
            O[(size_t)(r + 8) * Dn + cN + 1] = cc[3];
        }
}

// ---------------------------------------------------------------------------
// K4: new_state = state + SCALE * QR^T @ V
// grid (2, 64, 16)
// ---------------------------------------------------------------------------
__global__ void __launch_bounds__(256, 1) nstate_gemm(const float* __restrict__ state,
                                                      float* __restrict__ outns) {
    extern __shared__ uint32_t smu[];
    uint32_t sb = smem_u32(smu);

    const int db = blockIdx.x, nb = blockIdx.y, bh = blockIdx.z, b = bh >> 2;
    const int n0 = nb * BM, d0 = db * BM;
    const int lane = threadIdx.x & 31, wid = threadIdx.x >> 5;
    const int gid = lane >> 2, tig = lane & 3;
    const int wm = (wid & 1) * 64, wn = (wid >> 1) * 32;

    const float* Asrc = g_qt + ((size_t)bh * Nn + n0) * Tn;
    const float* Bsrc = g_vt + ((size_t)b * Dn + d0) * Tn;

    float c[16][4] = {};
    gemm_main(sb, smu, Tn / BK,
              [&](int kt) { return SrcPair{Asrc + kt * BK, Tn, Bsrc + kt * BK, Tn}; },
              wm, wn, gid, tig, c);

    const float* St = state + ((size_t)bh * Nn + n0) * Dn + d0;
    float* O = outns + ((size_t)bh * Nn + n0) * Dn + d0;
#pragma unroll
    for (int im = 0; im < 4; ++im)
#pragma unroll
        for (int jn = 0; jn < 4; ++jn) {
            int r = wm + im * 16 + gid;
            int cN = wn + jn * 8 + tig * 2;
            float* cc = c[im * 4 + jn];
            O[(size_t)r * Dn + cN]           = St[(size_t)r * Dn + cN]           + SCALEF * cc[0];
            O[(size_t)r * Dn + cN + 1]       = St[(size_t)r * Dn + cN + 1]       + SCALEF * cc[1];
            O[(size_t)(r + 8) * Dn + cN]     = St[(size_t)(r + 8) * Dn + cN]     + SCALEF * cc[2];
            O[(size_t)(r + 8) * Dn + cN + 1] = St[(size_t)(r + 8) * Dn + cN + 1] + SCALEF * cc[3];
        }
}

}  // namespace

extern "C" void kernel_launch(void* const* d_in, const int* in_sizes, int n_in,
                              void* d_out, int out_size) {
    const float* Q     = (const float*)d_in[0];
    const float* V     = (const float*)d_in[1];
    const float* state = (const float*)d_in[2];
    const float* cosb  = (const float*)d_in[3];
    const float* sinb  = (const float*)d_in[4];
    float* out = (float*)d_out;

    cudaFuncSetAttribute(scores_gemm, cudaFuncAttributeMaxDynamicSharedMemorySize, SMEM_TOTAL);
    cudaFuncSetAttribute(out_gemm,    cudaFuncAttributeMaxDynamicSharedMemorySize, SMEM_TOTAL);
    cudaFuncSetAttribute(nstate_gemm, cudaFuncAttributeMaxDynamicSharedMemorySize, SMEM_TOTAL);

    rope_kernel<<<dim3(Nn / 64, Tn / 32, BHn), 256>>>(Q, cosb, sinb);
    stateT_kernel<<<dim3(Nn / 32, Dn / 32, BHn), 256>>>(state);
    vT_kernel<<<dim3(Tn / 32, Dn / 32, Bz), 256>>>(V);

    scores_gemm<<<dim3(4, 4, BHn), 256, SMEM_TOTAL>>>();
    out_gemm<<<dim3(2, 4, BHn), 256, SMEM_TOTAL>>>(out);
    nstate_gemm<<<dim3(2, Nn / BM, BHn), 256, SMEM_TOTAL>>>(
        state, out + (size_t)BHn * Tn * Dn);
}

// round 11
// speedup vs baseline: 1.8411x; 1.0765x over previous
#include <cuda_runtime.h>
#include <cstdint>

namespace {

constexpr int Bz  = 4;
constexpr int NHn = 4;
constexpr int Tn  = 512;
constexpr int Dn  = 256;
constexpr int Nn  = 8192;
constexpr int BHn = Bz * NHn;
constexpr float SCALEF = 0.011048543456039806f;  // N^-0.5

// Scratch (device globals; allocation-free). All values tf32-pre-rounded fp32.
__device__ float g_qr[(size_t)BHn * Tn * Nn];   // RoPE(Q)    (t,n)
__device__ float g_qt[(size_t)BHn * Nn * Tn];   // RoPE(Q)^T  (n,t)
__device__ float g_st[(size_t)BHn * Dn * Nn];   // state^T    (d,n)
__device__ float g_vt[(size_t)Bz * Dn * Tn];    // V^T        (d,t)
__device__ float g_sc[(size_t)BHn * Tn * Tn];   // masked scores (t,s)

// ---------------------------------------------------------------------------
// Tiling: BM=BN=128, BK=32. SMEM tiles [128 rows][36 words].
// 8 warps as 2(m) x 4(n); warp tile 64x32. 3-stage cp.async pipeline,
// 2 CTAs per SM for latency hiding.
// ---------------------------------------------------------------------------
constexpr int BM = 128, BK = 32;
constexpr int RSTR = 36;
constexpr int TILE_WORDS = BM * RSTR;            // 4608
constexpr int STG = 3;
constexpr int SMEM_TOTAL = STG * 2 * TILE_WORDS * 4;   // 110592 B

__device__ __forceinline__ uint32_t f2t(float x) {
    uint32_t u;
    asm("cvt.rna.tf32.f32 %0, %1;" : "=r"(u) : "f"(x));
    return u;
}
__device__ __forceinline__ float f2tf(float x) { return __uint_as_float(f2t(x)); }

__device__ __forceinline__ uint32_t smem_u32(const void* p) {
    uint32_t a;
    asm("{ .reg .u64 t; cvta.to.shared.u64 t, %1; cvt.u32.u64 %0, t; }"
        : "=r"(a) : "l"(p));
    return a;
}

__device__ __forceinline__ void mma_tf32(float c[4], const uint32_t a[4],
                                         const uint32_t b[2]) {
    asm volatile(
        "mma.sync.aligned.m16n8k8.row.col.f32.tf32.tf32.f32 "
        "{%0,%1,%2,%3}, {%4,%5,%6,%7}, {%8,%9}, {%0,%1,%2,%3};"
        : "+f"(c[0]), "+f"(c[1]), "+f"(c[2]), "+f"(c[3])
        : "r"(a[0]), "r"(a[1]), "r"(a[2]), "r"(a[3]), "r"(b[0]), "r"(b[1]));
}

// One k-octet of the 64x32 warp tile. A,B both [128][36] row-major.
__device__ __forceinline__ void mma_oct(const uint32_t* __restrict__ As,
                                        const uint32_t* __restrict__ Bs,
                                        int ko, int wm, int wn,
                                        int gid, int tig, float c[16][4]) {
    uint32_t a[4][4], b[4][2];
#pragma unroll
    for (int im = 0; im < 4; ++im) {
        const uint32_t* pa = As + (wm + im * 16 + gid) * RSTR + ko + tig;
        a[im][0] = pa[0];
        a[im][1] = pa[8 * RSTR];
        a[im][2] = pa[4];
        a[im][3] = pa[8 * RSTR + 4];
    }
#pragma unroll
    for (int jn = 0; jn < 4; ++jn) {
        const uint32_t* pb = Bs + (wn + jn * 8 + gid) * RSTR + ko + tig;
        b[jn][0] = pb[0];
        b[jn][1] = pb[4];
    }
#pragma unroll
    for (int im = 0; im < 4; ++im)
#pragma unroll
        for (int jn = 0; jn < 4; ++jn)
            mma_tf32(c[im * 4 + jn], a[im], b[jn]);
}

// cp.async one [128][32] fp32 tile (k contiguous in source, row stride ld).
__device__ __forceinline__ void cp_tile(uint32_t dbase,
                                        const float* __restrict__ src, int ld) {
#pragma unroll
    for (int i = 0; i < 4; ++i) {
        int ch = threadIdx.x + i * 256;
        int row = ch >> 3, kc = (ch & 7) * 4;
        uint32_t d = dbase + (uint32_t)((row * RSTR + kc) * 4);
        asm volatile("cp.async.cg.shared.global [%0], [%1], 16;"
                     :: "r"(d), "l"(src + (size_t)row * ld + kc));
    }
}
#define CP_COMMIT() asm volatile("cp.async.commit_group;" ::: "memory")
#define CP_WAIT1()  asm volatile("cp.async.wait_group 1;" ::: "memory")

// ---------------------------------------------------------------------------
// Shared GEMM mainloop driver. Fetch(kt) -> {A ptr, lda, B ptr, ldb}.
// ---------------------------------------------------------------------------
struct SrcPair { const float* a; int la; const float* b; int lb; };

template <typename F>
__device__ __forceinline__ void gemm_main(uint32_t sb, const uint32_t* smu,
                                          int KT, F fetch_src,
                                          int wm, int wn, int gid, int tig,
                                          float c[16][4]) {
    auto saddr = [&](int st, int ab) {
        return sb + (uint32_t)(((st * 2 + ab) * TILE_WORDS) * 4);
    };
#pragma unroll
    for (int p = 0; p < STG - 1; ++p) {
        if (p < KT) {
            SrcPair s = fetch_src(p);
            cp_tile(saddr(p, 0), s.a, s.la);
            cp_tile(saddr(p, 1), s.b, s.lb);
        }
        CP_COMMIT();
    }
    int rs = 0;  // read stage
    for (int kt = 0; kt < KT; ++kt) {
        CP_WAIT1();
        __syncthreads();
        int pf = kt + STG - 1;
        if (pf < KT) {
            int ws = rs + STG - 1;
            if (ws >= STG) ws -= STG;
            SrcPair s = fetch_src(pf);
            cp_tile(saddr(ws, 0), s.a, s.la);
            cp_tile(saddr(ws, 1), s.b, s.lb);
        }
        CP_COMMIT();
        const uint32_t* As = smu + (size_t)rs * 2 * TILE_WORDS;
        const uint32_t* Bs = As + TILE_WORDS;
#pragma unroll
        for (int ko = 0; ko < BK; ko += 8)
            mma_oct(As, Bs, ko, wm, wn, gid, tig, c);
        if (++rs == STG) rs = 0;
    }
}

// ---------------------------------------------------------------------------
// K1: RoPE -> g_qr (t,n) and g_qt (n,t), tf32-rounded
// ---------------------------------------------------------------------------
__global__ void rope_kernel(const float* __restrict__ Q,
                            const float* __restrict__ C,
                            const float* __restrict__ S) {
    __shared__ float tile[32][65];
    const int bh = blockIdx.z, t0 = blockIdx.y * 32, n0 = blockIdx.x * 64;
    const int tid = threadIdx.x;
    const size_t qbase = ((size_t)bh * Tn + t0) * Nn + n0;
#pragma unroll
    for (int i = 0; i < 4; ++i) {
        int p  = tid + i * 256;
        int tt = p >> 5, pi = p & 31;
        int nn = pi * 2;
        float2 q = *reinterpret_cast<const float2*>(Q + qbase + (size_t)tt * Nn + nn);
        float2 c = *reinterpret_cast<const float2*>(C + (size_t)(t0 + tt) * Nn + n0 + nn);
        float2 s = *reinterpret_cast<const float2*>(S + (size_t)(t0 + tt) * Nn + n0 + nn);
        float2 r;
        r.x = f2tf(q.x * c.x - q.y * s.x);
        r.y = f2tf(q.y * c.y + q.x * s.y);
        *reinterpret_cast<float2*>(g_qr + qbase + (size_t)tt * Nn + nn) = r;
        tile[tt][nn] = r.x;
        tile[tt][nn + 1] = r.y;
    }
    __syncthreads();
    const size_t tbase = ((size_t)bh * Nn + n0) * Tn + t0;
#pragma unroll
    for (int i = 0; i < 8; ++i) {
        int e  = tid + i * 256;
        int nn = e >> 5, tt = e & 31;
        g_qt[tbase + (size_t)nn * Tn + tt] = tile[tt][nn];
    }
}

// K1b: state^T (d,n), tf32-rounded
__global__ void stateT_kernel(const float* __restrict__ St) {
    __shared__ float tile[32][33];
    const int bh = blockIdx.z, n0 = blockIdx.x * 32, d0 = blockIdx.y * 32;
    const int tid = threadIdx.x;
#pragma unroll
    for (int i = 0; i < 4; ++i) {
        int e = tid + i * 256;
        int nn = e >> 5, dd = e & 31;
        tile[nn][dd] = St[((size_t)bh * Nn + n0 + nn) * Dn + d0 + dd];
    }
    __syncthreads();
#pragma unroll
    for (int i = 0; i < 4; ++i) {
        int e = tid + i * 256;
        int dd = e >> 5, nn = e & 31;
        g_st[((size_t)bh * Dn + d0 + dd) * Nn + n0 + nn] = f2tf(tile[nn][dd]);
    }
}

// K1c: V^T (d,t), tf32-rounded
__global__ void vT_kernel(const float* __restrict__ V) {
    __shared__ float tile[32][33];
    const int b = blockIdx.z, t0 = blockIdx.x * 32, d0 = blockIdx.y * 32;
    const int tid = threadIdx.x;
#pragma unroll
    for (int i = 0; i < 4; ++i) {
        int e = tid + i * 256;
        int tt = e >> 5, dd = e & 31;
        tile[tt][dd] = V[((size_t)b * Tn + t0 + tt) * Dn + d0 + dd];
    }
    __syncthreads();
#pragma unroll
    for (int i = 0; i < 4; ++i) {
        int e = tid + i * 256;
        int dd = e >> 5, tt = e & 31;
        g_vt[((size_t)b * Dn + d0 + dd) * Tn + t0 + tt] = f2tf(tile[tt][dd]);
    }
}

// ---------------------------------------------------------------------------
// K2: scores = mask(QR @ QR^T) * SCALE (lower-tri tiles only), tf32-rounded
// grid (4, 4, 16)
// ---------------------------------------------------------------------------
__global__ void __launch_bounds__(256, 2) scores_gemm() {
    const int sb_ = blockIdx.x, tb = blockIdx.y, bh = blockIdx.z;
    if (sb_ > tb) return;
    extern __shared__ uint32_t smu[];
    uint32_t sb = smem_u32(smu);

    const int t0 = tb * BM, s0 = sb_ * BM;
    const int lane = threadIdx.x & 31, wid = threadIdx.x >> 5;
    const int gid = lane >> 2, tig = lane & 3;
    const int wm = (wid & 1) * 64, wn = (wid >> 1) * 32;
    const float* Asrc = g_qr + ((size_t)bh * Tn + t0) * Nn;
    const float* Bsrc = g_qr + ((size_t)bh * Tn + s0) * Nn;

    float c[16][4] = {};
    gemm_main(sb, smu, Nn / BK,
              [&](int kt) { return SrcPair{Asrc + kt * BK, Nn, Bsrc + kt * BK, Nn}; },
              wm, wn, gid, tig, c);

    float* Sc = g_sc + (size_t)bh * Tn * Tn;
#pragma unroll
    for (int im = 0; im < 4; ++im)
#pragma unroll
        for (int jn = 0; jn < 4; ++jn) {
            int t = t0 + wm + im * 16 + gid;
            int s = s0 + wn + jn * 8 + tig * 2;
            float* cc = c[im * 4 + jn];
            Sc[(size_t)t * Tn + s]           = (s     < t) ? f2tf(cc[0] * SCALEF) : 0.f;
            Sc[(size_t)t * Tn + s + 1]       = (s + 1 < t) ? f2tf(cc[1] * SCALEF) : 0.f;
            Sc[(size_t)(t + 8) * Tn + s]     = (s     < t + 8) ? f2tf(cc[2] * SCALEF) : 0.f;
            Sc[(size_t)(t + 8) * Tn + s + 1] = (s + 1 < t + 8) ? f2tf(cc[3] * SCALEF) : 0.f;
        }
}

// ---------------------------------------------------------------------------
// K3: out = scores @ V + QR @ state  (two K-segments, one accumulator)
// grid (2, 4, 16)
// ---------------------------------------------------------------------------
__global__ void __launch_bounds__(256, 2) out_gemm(float* __restrict__ out) {
    extern __shared__ uint32_t smu[];
    uint32_t sb = smem_u32(smu);

    const int db = blockIdx.x, tb = blockIdx.y, bh = blockIdx.z, b = bh >> 2;
    const int t0 = tb * BM, d0 = db * BM;
    const int lane = threadIdx.x & 31, wid = threadIdx.x >> 5;
    const int gid = lane >> 2, tig = lane & 3;
    const int wm = (wid & 1) * 64, wn = (wid >> 1) * 32;

    const float* A1 = g_sc + ((size_t)bh * Tn + t0) * Tn;
    const float* B1 = g_vt + ((size_t)b * Dn + d0) * Tn;
    const float* A2 = g_qr + ((size_t)bh * Tn + t0) * Nn;
    const float* B2 = g_st + ((size_t)bh * Dn + d0) * Nn;

    const int KT1 = (tb + 1) * (BM / BK);   // causal trim
    const int KT = KT1 + Nn / BK;

    float c[16][4] = {};
    gemm_main(sb, smu, KT,
              [&](int kt) {
                  if (kt < KT1)
                      return SrcPair{A1 + kt * BK, Tn, B1 + kt * BK, Tn};
                  int k2 = kt - KT1;
                  return SrcPair{A2 + k2 * BK, Nn, B2 + k2 * BK, Nn};
              },
              wm, wn, gid, tig, c);

    float* O = out + ((size_t)bh * Tn + t0) * Dn + d0;
#pragma unroll
    for (int im = 0; im < 4; ++im)
#pragma unroll
        for (int jn = 0; jn < 4; ++jn) {
            int r = wm + im * 16 + gid;
            int cN = wn + jn * 8 + tig * 2;
            float* cc = c[im * 4 + jn];
            O[(size_t)r * Dn + cN]           = cc[0];
            O[(size_t)r * Dn + cN + 1]       = cc[1];
            O[(size_t)(r + 8) * Dn + cN]     = cc[2];
            O[(size_t)(r + 8) * Dn + cN + 1] = cc[3];
        }
}

// ---------------------------------------------------------------------------
// K4: new_state = state + SCALE * QR^T @ V
// grid (2, 64, 16)
// ---------------------------------------------------------------------------
__global__ void __launch_bounds__(256, 2) nstate_gemm(const float* __restrict__ state,
                                                      float* __restrict__ outns) {
    extern __shared__ uint32_t smu[];
    uint32_t sb = smem_u32(smu);

    const int db = blockIdx.x, nb = blockIdx.y, bh = blockIdx.z, b = bh >> 2;
    const int n0 = nb * BM, d0 = db * BM;
    const int lane = threadIdx.x & 31, wid = threadIdx.x >> 5;
    const int gid = lane >> 2, tig = lane & 3;
    const int wm = (wid & 1) * 64, wn = (wid >> 1) * 32;

    const float* Asrc = g_qt + ((size_t)bh * Nn + n0) * Tn;
    const float* Bsrc = g_vt + ((size_t)b * Dn + d0) * Tn;

    float c[16][4] = {};
    gemm_main(sb, smu, Tn / BK,
              [&](int kt) { return SrcPair{Asrc + kt * BK, Tn, Bsrc + kt * BK, Tn}; },
              wm, wn, gid, tig, c);

    const float* St = state + ((size_t)bh * Nn + n0) * Dn + d0;
    float* O = outns + ((size_t)bh * Nn + n0) * Dn + d0;
#pragma unroll
    for (int im = 0; im < 4; ++im)
#pragma unroll
        for (int jn = 0; jn < 4; ++jn) {
            int r = wm + im * 16 + gid;
            int cN = wn + jn * 8 + tig * 2;
            float* cc = c[im * 4 + jn];
            O[(size_t)r * Dn + cN]           = St[(size_t)r * Dn + cN]           + SCALEF * cc[0];
            O[(size_t)r * Dn + cN + 1]       = St[(size_t)r * Dn + cN + 1]       + SCALEF * cc[1];
            O[(size_t)(r + 8) * Dn + cN]     = St[(size_t)(r + 8) * Dn + cN]     + SCALEF * cc[2];
            O[(size_t)(r + 8) * Dn + cN + 1] = St[(size_t)(r + 8) * Dn + cN + 1] + SCALEF * cc[3];
        }
}

}  // namespace

extern "C" void kernel_launch(void* const* d_in, const int* in_sizes, int n_in,
                              void* d_out, int out_size) {
    const float* Q     = (const float*)d_in[0];
    const float* V     = (const float*)d_in[1];
    const float* state = (const float*)d_in[2];
    const float* cosb  = (const float*)d_in[3];
    const float* sinb  = (const float*)d_in[4];
    float* out = (float*)d_out;

    cudaFuncSetAttribute(scores_gemm, cudaFuncAttributeMaxDynamicSharedMemorySize, SMEM_TOTAL);
    cudaFuncSetAttribute(out_gemm,    cudaFuncAttributeMaxDynamicSharedMemorySize, SMEM_TOTAL);
    cudaFuncSetAttribute(nstate_gemm, cudaFuncAttributeMaxDynamicSharedMemorySize, SMEM_TOTAL);

    rope_kernel<<<dim3(Nn / 64, Tn / 32, BHn), 256>>>(Q, cosb, sinb);
    stateT_kernel<<<dim3(Nn / 32, Dn / 32, BHn), 256>>>(state);
    vT_kernel<<<dim3(Tn / 32, Dn / 32, Bz), 256>>>(V);

    scores_gemm<<<dim3(4, 4, BHn), 256, SMEM_TOTAL>>>();
    out_gemm<<<dim3(2, 4, BHn), 256, SMEM_TOTAL>>>(out);
    nstate_gemm<<<dim3(2, Nn / BM, BHn), 256, SMEM_TOTAL>>>(
        state, out + (size_t)BHn * Tn * Dn);
}